// round 9
// baseline (speedup 1.0000x reference)
#include <cuda_runtime.h>
#include <math.h>

#define T_TREES 128
#define B_BATCH 1024
#define D_FEAT  784
#define K_TOP   200
#define D4      (D_FEAT / 4)   // 196

#define BT 8            // batch rows per tile
#define TT 4            // tree rows per tile
#define NJ 7            // ceil(BT*D4 / 256)
#define NTILES 4096     // (1024/BT) * (128/TT)
#define NSEL   16       // selection blocks (8 trees each)

#define NSLOT 25        // ceil(784/32)

// Flag state, reset by the last-exiting block each launch (replay-safe).
__device__ unsigned g_done = 0;   // selection blocks completed (0..NSEL)
__device__ unsigned g_exit = 0;   // blocks finished (0..NTILES)

// Selected attention matrix [T, D] (kernel-internal hand-off).
__device__ float4 g_attn4[T_TREES * D4];

// ---------------------------------------------------------------------------
// Fused kernel. Blocks 0..NSEL-1 first run warp-per-tree top-K selection
// (exact; jax.lax.top_k tie semantics: lowest index wins) with their keys in
// SHARED memory — the same buffer later reused as the attn tile — so the
// select path adds no register pressure to the store path. All other blocks
// prefetch their x float4s while selection runs, then spin on g_done.
// Store path is identical to the best (R4) broadcast kernel.
// ---------------------------------------------------------------------------
__global__ __launch_bounds__(256) void fused_kernel(
    const float4* __restrict__ x4, const float* __restrict__ mask,
    float4* __restrict__ o4, float4* __restrict__ attn_tail4)
{
    __shared__ union {
        float4   sa[TT * D4];             // 12544 B (store phase)
        unsigned keys[8 * NSLOT * 32];    // 25600 B (select phase)
    } su;

    const int tb   = blockIdx.x;
    const int tid  = threadIdx.x;
    const int wid  = tid >> 5;
    const int lane = tid & 31;

    const int t0 = (tb & 31) * TT;       // 32 t-tiles
    const int b0 = (tb >> 5) * BT;       // 128 b-tiles

    if (tb < NSEL) {
        // ---- Phase 1 (16 blocks): one warp per tree, keys in smem --------
        const int t = tb * 8 + wid;
        const float* row = mask + t * D_FEAT;
        unsigned* kb = su.keys + wid * (NSLOT * 32);  // warp-private region

        #pragma unroll
        for (int i = 0; i < NSLOT; i++) {
            int d = i * 32 + lane;
            unsigned k = 0u;
            if (d < D_FEAT) {
                float m = row[d];
                float s = 1.0f / (1.0f + expf(-m));
                k = __float_as_uint(s);   // s in (0,1): monotone uint key
            }
            kb[i * 32 + lane] = k;        // thread-private slot, no sync
        }

        // K-th largest key: max lo with count(key >= lo) >= K.
        // mask ~ U[-1,1) -> s in (0.2689, 0.7311); bracket with slack.
        unsigned lo = 0x3E800000u, hi = 0x3F3C0000u;
        while (lo < hi) {
            unsigned mid = lo + ((hi - lo + 1u) >> 1);
            int c = 0;
            #pragma unroll 5
            for (int i = 0; i < NSLOT; i++) c += (kb[i * 32 + lane] >= mid);
            c = __reduce_add_sync(0xFFFFFFFFu, c);
            if (c >= K_TOP) lo = mid; else hi = mid - 1u;
        }

        int cg = 0;
        #pragma unroll 5
        for (int i = 0; i < NSLOT; i++) cg += (kb[i * 32 + lane] > lo);
        cg = __reduce_add_sync(0xFFFFFFFFu, cg);
        const int need = K_TOP - cg;

        float* g_attn = (float*)g_attn4;
        const unsigned below = (1u << lane) - 1u;
        int running = 0;
        #pragma unroll 5
        for (int i = 0; i < NSLOT; i++) {
            int d = i * 32 + lane;
            unsigned key = kb[i * 32 + lane];
            bool tie = (key == lo) && (d < D_FEAT);
            unsigned bm = __ballot_sync(0xFFFFFFFFu, tie);
            int rank = running + __popc(bm & below);
            bool keep = (key > lo) || (tie && rank < need);
            running += __popc(bm);
            if (d < D_FEAT)
                g_attn[t * D_FEAT + d] = keep ? __uint_as_float(key) : 0.0f;
        }
        __threadfence();                  // publish g_attn
        __syncthreads();                  // also: done with su.keys
        if (tid == 0) atomicAdd(&g_done, 1u);
    }

    // ---- All blocks: prefetch x (overlaps selection for non-select blocks)
    float4 xv[NJ];
    #pragma unroll
    for (int k = 0; k < NJ; k++) {
        int j = tid + k * 256;
        if (j < BT * D4) xv[k] = __ldg(&x4[b0 * D4 + j]);
    }

    // ---- Wait for selection completion ------------------------------------
    if (tid == 0) {
        volatile unsigned* dp = &g_done;
        while (*dp < NSEL) __nanosleep(64);
    }
    __syncthreads();
    __threadfence();   // acquire: g_attn writes visible

    // ---- Store phase (identical to R4 bcast) -------------------------------
    for (int j = tid; j < TT * D4; j += 256) {
        float4 a = g_attn4[t0 * D4 + j];     // rows t0..t0+3 contiguous
        su.sa[j] = a;
        if (b0 == 0) attn_tail4[t0 * D4 + j] = a;   // attention output
    }
    __syncthreads();

    #pragma unroll
    for (int k = 0; k < NJ; k++) {
        int j = tid + k * 256;
        if (j >= BT * D4) break;
        const int bl = j / D4;
        const int d4 = j - bl * D4;
        const float4 v = xv[k];
        const int base = ((b0 + bl) * T_TREES + t0) * D4 + d4;
        #pragma unroll
        for (int tl = 0; tl < TT; tl++) {
            float4 av = su.sa[tl * D4 + d4];
            float4 r;
            r.x = v.x * av.x;
            r.y = v.y * av.y;
            r.z = v.z * av.z;
            r.w = v.w * av.w;
            __stcs(&o4[base + tl * D4], r);
        }
    }

    // ---- Reset flag state for the next replay (last block out) ------------
    __syncthreads();
    if (tid == 0) {
        unsigned f = atomicAdd(&g_exit, 1u);
        if (f == NTILES - 1u) {
            g_done = 0;
            g_exit = 0;
            __threadfence();
        }
    }
}

extern "C" void kernel_launch(void* const* d_in, const int* in_sizes, int n_in,
                              void* d_out, int out_size)
{
    const float* x    = (const float*)d_in[0];
    const float* mask = (const float*)d_in[1];
    if (n_in >= 2 && in_sizes[0] == T_TREES * D_FEAT) {
        x    = (const float*)d_in[1];
        mask = (const float*)d_in[0];
    }

    float* out = (float*)d_out;
    float* attn_tail = out + (size_t)B_BATCH * T_TREES * D_FEAT;

    fused_kernel<<<NTILES, 256>>>((const float4*)x, mask,
                                  (float4*)out, (float4*)attn_tail);
}

// round 10
// speedup vs baseline: 1.1043x; 1.1043x over previous
#include <cuda_runtime.h>
#include <math.h>

#define T_TREES 128
#define B_BATCH 1024
#define D_FEAT  784
#define K_TOP   200
#define D4      (D_FEAT / 4)   // 196

#define BT 8   // batch rows per tile
#define TT 4   // tree rows per tile
#define NJ 7   // ceil(BT*D4 / 256)

#define NSLOT 25   // ceil(784/32)

// Selected attention matrix [T, D], float4-aligned (kernel hand-off).
__device__ float4 g_attn4[T_TREES * D4];

// ---------------------------------------------------------------------------
// Kernel 1: per-tree top-K selection, ONE WARP PER TREE. Minimal critical
// path: writes ONLY g_attn. Exact K-th key via binary search on the uint
// bits of sigmoid(m) (s>0 -> monotone key); ties at the K-th value broken
// lowest-index-first (jax.lax.top_k semantics).
// ---------------------------------------------------------------------------
__global__ __launch_bounds__(32) void attn_select_kernel(
    const float* __restrict__ mask)
{
    const int t    = blockIdx.x;
    const int lane = threadIdx.x;
    const float* row = mask + t * D_FEAT;

    unsigned keys[NSLOT];
    #pragma unroll
    for (int i = 0; i < NSLOT; i++) {
        int d = i * 32 + lane;
        if (d < D_FEAT) {
            float m = row[d];
            float s = 1.0f / (1.0f + expf(-m));
            keys[i] = __float_as_uint(s);   // s in (0,1): monotone uint key
        } else {
            keys[i] = 0u;
        }
    }

    // K-th largest key: max lo with count(key >= lo) >= K.
    // mask ~ U[-1,1) -> s in (0.2689, 0.7311); bracket with slack.
    unsigned lo = 0x3E800000u, hi = 0x3F3C0000u;
    while (lo < hi) {
        unsigned mid = lo + ((hi - lo + 1u) >> 1);
        int c = 0;
        #pragma unroll
        for (int i = 0; i < NSLOT; i++) c += (keys[i] >= mid);
        c = __reduce_add_sync(0xFFFFFFFFu, c);
        if (c >= K_TOP) lo = mid; else hi = mid - 1u;
    }

    int cg = 0;
    #pragma unroll
    for (int i = 0; i < NSLOT; i++) cg += (keys[i] > lo);
    cg = __reduce_add_sync(0xFFFFFFFFu, cg);
    const int need = K_TOP - cg;

    float* g_attn = (float*)g_attn4;
    const unsigned below = (1u << lane) - 1u;
    int running = 0;
    #pragma unroll
    for (int i = 0; i < NSLOT; i++) {
        int d = i * 32 + lane;
        bool tie = (keys[i] == lo) && (d < D_FEAT);
        unsigned bm = __ballot_sync(0xFFFFFFFFu, tie);
        int rank = running + __popc(bm & below);
        bool keep = (keys[i] > lo) || (tie && rank < need);
        running += __popc(bm);
        if (d < D_FEAT)
            g_attn[t * D_FEAT + d] = keep ? __uint_as_float(keys[i]) : 0.0f;
    }
}

// ---------------------------------------------------------------------------
// Kernel 2: out[b,t,d] = x[b,d] * attn[t,d]. Best measured store engine:
// x float4s prefetched into registers (load MLP), attn tile staged in smem
// (8x reuse across BT batch rows), streaming 128-bit stores (output never
// re-read). Blocks with b0==0 also emit the attention output copy.
// ---------------------------------------------------------------------------
__global__ __launch_bounds__(256) void bcast_mul_kernel(
    const float4* __restrict__ x4, float4* __restrict__ o4,
    float4* __restrict__ attn_tail4)
{
    __shared__ float4 sa[TT * D4];  // 12544 B

    const int tb  = blockIdx.x;
    const int t0  = (tb & 31) * TT;        // 128/TT = 32 t-tiles
    const int b0  = (tb >> 5) * BT;        // 1024/BT = 128 b-tiles
    const int tid = threadIdx.x;

    // Prefetch this thread's x elements (independent of the attn fill).
    float4 xv[NJ];
    #pragma unroll
    for (int k = 0; k < NJ; k++) {
        int j = tid + k * 256;
        if (j < BT * D4) xv[k] = __ldg(&x4[b0 * D4 + j]);  // (b0+bl)*D4+d4
    }

    for (int j = tid; j < TT * D4; j += 256) {
        float4 a = g_attn4[t0 * D4 + j];   // rows t0..t0+3 contiguous
        sa[j] = a;
        if (b0 == 0) attn_tail4[t0 * D4 + j] = a;  // attention output
    }
    __syncthreads();

    #pragma unroll
    for (int k = 0; k < NJ; k++) {
        int j = tid + k * 256;
        if (j >= BT * D4) break;
        const int bl = j / D4;
        const int d4 = j - bl * D4;
        const float4 v = xv[k];
        const int base = ((b0 + bl) * T_TREES + t0) * D4 + d4;
        #pragma unroll
        for (int tl = 0; tl < TT; tl++) {
            float4 av = sa[tl * D4 + d4];
            float4 r;
            r.x = v.x * av.x;
            r.y = v.y * av.y;
            r.z = v.z * av.z;
            r.w = v.w * av.w;
            __stcs(&o4[base + tl * D4], r);
        }
    }
}

extern "C" void kernel_launch(void* const* d_in, const int* in_sizes, int n_in,
                              void* d_out, int out_size)
{
    const float* x    = (const float*)d_in[0];
    const float* mask = (const float*)d_in[1];
    if (n_in >= 2 && in_sizes[0] == T_TREES * D_FEAT) {
        x    = (const float*)d_in[1];
        mask = (const float*)d_in[0];
    }

    float* out = (float*)d_out;
    float* attn_tail = out + (size_t)B_BATCH * T_TREES * D_FEAT;

    attn_select_kernel<<<T_TREES, 32>>>(mask);
    bcast_mul_kernel<<<(B_BATCH / BT) * (T_TREES / TT), 256>>>(
        (const float4*)x, (float4*)out, (float4*)attn_tail);
}

// round 11
// speedup vs baseline: 1.1146x; 1.0094x over previous
#include <cuda_runtime.h>
#include <math.h>

#define T_TREES 128
#define B_BATCH 1024
#define D_FEAT  784
#define K_TOP   200
#define D4      (D_FEAT / 4)   // 196

#define BT 4            // batch rows per tile
#define TT 4            // tree rows per tile
#define NJ 4            // ceil(BT*D4 / 256) = ceil(784/256)
#define NTILES ((B_BATCH / BT) * (T_TREES / TT))   // 8192
#define NTAIL  (T_TREES / TT)                      // 32 attn-copy blocks

#define NSLOT 25   // ceil(784/32)

// Selected attention matrix [T, D], float4-aligned (kernel hand-off).
__device__ float4 g_attn4[T_TREES * D4];

// ---------------------------------------------------------------------------
// Kernel 1: per-tree top-K selection, ONE WARP PER TREE. Writes ONLY g_attn.
// Exact K-th key via binary search on the uint bits of sigmoid(m) (s>0 ->
// monotone key); ties broken lowest-index-first (jax.lax.top_k semantics).
// ---------------------------------------------------------------------------
__global__ __launch_bounds__(32) void attn_select_kernel(
    const float* __restrict__ mask)
{
    const int t    = blockIdx.x;
    const int lane = threadIdx.x;
    const float* row = mask + t * D_FEAT;

    unsigned keys[NSLOT];
    #pragma unroll
    for (int i = 0; i < NSLOT; i++) {
        int d = i * 32 + lane;
        if (d < D_FEAT) {
            float m = row[d];
            float s = 1.0f / (1.0f + expf(-m));
            keys[i] = __float_as_uint(s);   // s in (0,1): monotone uint key
        } else {
            keys[i] = 0u;
        }
    }

    // K-th largest key: max lo with count(key >= lo) >= K.
    // mask ~ U[-1,1) -> s in (0.2689, 0.7311); bracket with slack.
    unsigned lo = 0x3E800000u, hi = 0x3F3C0000u;
    while (lo < hi) {
        unsigned mid = lo + ((hi - lo + 1u) >> 1);
        int c = 0;
        #pragma unroll
        for (int i = 0; i < NSLOT; i++) c += (keys[i] >= mid);
        c = __reduce_add_sync(0xFFFFFFFFu, c);
        if (c >= K_TOP) lo = mid; else hi = mid - 1u;
    }

    int cg = 0;
    #pragma unroll
    for (int i = 0; i < NSLOT; i++) cg += (keys[i] > lo);
    cg = __reduce_add_sync(0xFFFFFFFFu, cg);
    const int need = K_TOP - cg;

    float* g_attn = (float*)g_attn4;
    const unsigned below = (1u << lane) - 1u;
    int running = 0;
    #pragma unroll
    for (int i = 0; i < NSLOT; i++) {
        int d = i * 32 + lane;
        bool tie = (keys[i] == lo) && (d < D_FEAT);
        unsigned bm = __ballot_sync(0xFFFFFFFFu, tie);
        int rank = running + __popc(bm & below);
        bool keep = (keys[i] > lo) || (tie && rank < need);
        running += __popc(bm);
        if (d < D_FEAT)
            g_attn[t * D_FEAT + d] = keep ? __uint_as_float(keys[i]) : 0.0f;
    }
}

// ---------------------------------------------------------------------------
// Kernel 2: out[b,t,d] = x[b,d] * attn[t,d]. BT=4 tile cuts the register
// prefetch to xv[4] (16 regs) to raise occupancy vs the BT=8 version.
// attn tile staged in smem (BT x reuse), streaming 128-bit stores (output
// never re-read). The last NTAIL blocks only copy attn to its output slot.
// ---------------------------------------------------------------------------
__global__ __launch_bounds__(256) void bcast_mul_kernel(
    const float4* __restrict__ x4, float4* __restrict__ o4,
    float4* __restrict__ attn_tail4)
{
    __shared__ float4 sa[TT * D4];  // 12544 B

    const int tb  = blockIdx.x;
    const int tid = threadIdx.x;

    if (tb >= NTILES) {              // attention-output copy blocks
        const int tt0 = (tb - NTILES) * TT;
        for (int j = tid; j < TT * D4; j += 256)
            attn_tail4[tt0 * D4 + j] = g_attn4[tt0 * D4 + j];
        return;
    }

    const int t0 = (tb & 31) * TT;        // 128/TT = 32 t-tiles
    const int b0 = (tb >> 5) * BT;        // 1024/BT = 256 b-tiles

    // Prefetch this thread's x elements (independent of the attn fill).
    float4 xv[NJ];
    #pragma unroll
    for (int k = 0; k < NJ; k++) {
        int j = tid + k * 256;
        if (j < BT * D4) xv[k] = __ldg(&x4[b0 * D4 + j]);  // (b0+bl)*D4+d4
    }

    for (int j = tid; j < TT * D4; j += 256)
        sa[j] = g_attn4[t0 * D4 + j];     // rows t0..t0+3 contiguous
    __syncthreads();

    #pragma unroll
    for (int k = 0; k < NJ; k++) {
        int j = tid + k * 256;
        if (j >= BT * D4) break;
        const int bl = j / D4;
        const int d4 = j - bl * D4;
        const float4 v = xv[k];
        const int base = ((b0 + bl) * T_TREES + t0) * D4 + d4;
        #pragma unroll
        for (int tl = 0; tl < TT; tl++) {
            float4 av = sa[tl * D4 + d4];
            float4 r;
            r.x = v.x * av.x;
            r.y = v.y * av.y;
            r.z = v.z * av.z;
            r.w = v.w * av.w;
            __stcs(&o4[base + tl * D4], r);
        }
    }
}

extern "C" void kernel_launch(void* const* d_in, const int* in_sizes, int n_in,
                              void* d_out, int out_size)
{
    const float* x    = (const float*)d_in[0];
    const float* mask = (const float*)d_in[1];
    if (n_in >= 2 && in_sizes[0] == T_TREES * D_FEAT) {
        x    = (const float*)d_in[1];
        mask = (const float*)d_in[0];
    }

    float* out = (float*)d_out;
    float* attn_tail = out + (size_t)B_BATCH * T_TREES * D_FEAT;

    attn_select_kernel<<<T_TREES, 32>>>(mask);
    bcast_mul_kernel<<<NTILES + NTAIL, 256>>>(
        (const float4*)x, (float4*)out, (float4*)attn_tail);
}